// round 11
// baseline (speedup 1.0000x reference)
#include <cuda_runtime.h>
#include <cuda_bf16.h>
#include <cstdint>

// Problem constants (fixed shapes from reference setup_inputs)
#define BB 8
#define SS 4096
#define DD 512
#define HH 512
#define H2 1024
#define MM (BB * SS)   // 32768
#define NCH 4096       // B*H chains
#define NC 64          // chunks per chain
#define CT 64          // steps per chunk

#define KK 512         // GEMM K (both layers)
#define NKT 16         // K tiles of 32
#define GBM 256        // CTA M tile
#define GBN 128        // CTA N tile
#define NTHR 512       // threads per CTA (16 warps)
#define ROWW 36        // smem row stride in words (32 + pad 4)
#define STW ((GBM + GBN) * ROWW)        // words per stage = 13824
#define NSTG 3
#define DYN_SMEM (NSTG * STW * 4)       // 165888 B

// Scratch
__device__ float g_gh[(long long)MM * H2];
__device__ float g_h1[(long long)MM * HH];
__device__ float g_A[NC * NCH];
__device__ float g_B[NC * NCH];
__device__ float g_Hi[NC * NCH];
__device__ float g_w0r[H2 * DD];
__device__ float g_w1r[H2 * HH];

__device__ __forceinline__ uint32_t smem_u32(const void* p) {
    uint32_t a;
    asm("{ .reg .u64 t; cvta.to.shared.u64 t, %1; cvt.u32.u64 %0, t; }"
        : "=r"(a) : "l"(p));
    return a;
}
__device__ __forceinline__ uint32_t f2tf32(float x) {
    uint32_t r;
    asm("cvt.rna.tf32.f32 %0, %1;" : "=r"(r) : "f"(x));
    return r;
}
#define CP_ASYNC16(dst, src) \
    asm volatile("cp.async.cg.shared.global [%0], [%1], 16;\n" \
                 :: "r"(dst), "l"(src) : "memory")
#define CP_COMMIT() asm volatile("cp.async.commit_group;\n" ::: "memory")
#define CP_WAIT1()  asm volatile("cp.async.wait_group 1;\n" ::: "memory")

__device__ __forceinline__ void mma_tf32(float* c, const uint32_t* a, const uint32_t* b) {
    asm volatile(
        "mma.sync.aligned.m16n8k8.row.col.f32.tf32.tf32.f32 "
        "{%0,%1,%2,%3}, {%4,%5,%6,%7}, {%8,%9}, {%0,%1,%2,%3};"
        : "+f"(c[0]), "+f"(c[1]), "+f"(c[2]), "+f"(c[3])
        : "r"(a[0]), "r"(a[1]), "r"(a[2]), "r"(a[3]),
          "r"(b[0]), "r"(b[1]));
}

__global__ void __launch_bounds__(256) round_weights(
    const float* __restrict__ w, float* __restrict__ o)
{
    int i = (blockIdx.x * 256 + threadIdx.x) * 4;
    float4 v = *(const float4*)(w + i);
    uint4 t;
    t.x = f2tf32(v.x); t.y = f2tf32(v.y);
    t.z = f2tf32(v.z); t.w = f2tf32(v.w);
    *(uint4*)(o + i) = t;
}

// Issue cp.async for one 32-K stage: A 256 rows, W 128 rows, padded smem rows.
__device__ __forceinline__ void stage_copy(
    const float* __restrict__ A, const float* __restrict__ W,
    uint32_t sA, uint32_t sB, int bm, int bn, int kt, int tid)
{
    const float* Ab = A + (size_t)bm * KK + kt * 32;
    const float* Wb = W + (size_t)bn * KK + kt * 32;
#pragma unroll
    for (int i = 0; i < 4; i++) {               // 2048 granules of A
        int g = tid + NTHR * i;
        int row = g >> 3, q = g & 7;
        CP_ASYNC16(sA + row * (ROWW * 4) + q * 16,
                   Ab + (size_t)row * KK + q * 4);
    }
#pragma unroll
    for (int i = 0; i < 2; i++) {               // 1024 granules of W
        int g = tid + NTHR * i;
        int row = g >> 3, q = g & 7;
        CP_ASYNC16(sB + row * (ROWW * 4) + q * 16,
                   Wb + (size_t)row * KK + q * 4);
    }
    CP_COMMIT();
}

// C[M,1024] = A[M,512] * W[1024,512]^T + bias, tf32 mma.sync,
// block tile 256x128, 16 warps (4m x 4n), warp tile 64x32, 3-stage cp.async.
__global__ void __launch_bounds__(NTHR, 1) gemm_tf32(
    const float* __restrict__ A, const float* __restrict__ W,
    const float* __restrict__ bias, float* __restrict__ C)
{
    extern __shared__ uint32_t dyn[];

    const int tid    = threadIdx.x;
    const int wid    = tid >> 5;
    const int lane   = tid & 31;
    const int warp_m = wid >> 2;       // 0..3 -> 64 rows
    const int warp_n = wid & 3;        // 0..3 -> 32 cols
    const int bm     = blockIdx.y * GBM;
    const int bn     = blockIdx.x * GBN;
    const int r      = lane >> 2;      // 0..7
    const int cq     = lane & 3;       // 0..3

    const uint32_t sbase = smem_u32(dyn);

    float acc[4][4][4];
#pragma unroll
    for (int i = 0; i < 4; i++)
#pragma unroll
        for (int j = 0; j < 4; j++)
#pragma unroll
            for (int w = 0; w < 4; w++) acc[i][j][w] = 0.f;

    // Prefetch stages 0 and 1.
    stage_copy(A, W, sbase, sbase + GBM * ROWW * 4, bm, bn, 0, tid);
    stage_copy(A, W, sbase + STW * 4, sbase + (STW + GBM * ROWW) * 4, bm, bn, 1, tid);

    for (int kt = 0; kt < NKT; kt++) {
        const int s = kt % NSTG;
        CP_WAIT1();
        __syncthreads();

        // Prefetch kt+2 into stage (kt+2)%3 (last read at iter kt-1).
        if (kt + 2 < NKT) {
            const int sp = (kt + 2) % NSTG;
            stage_copy(A, W, sbase + sp * STW * 4,
                       sbase + (sp * STW + GBM * ROWW) * 4, bm, bn, kt + 2, tid);
        }

        const uint32_t* As = dyn + s * STW;
        const uint32_t* Bs = As + GBM * ROWW;

#pragma unroll
        for (int ks = 0; ks < 4; ks++) {
            const int kc = ks * 8 + cq;
            uint32_t a[4][4], b[4][2];
#pragma unroll
            for (int mt = 0; mt < 4; mt++) {
                int mb = warp_m * 64 + mt * 16;
                a[mt][0] = As[(mb + r) * ROWW + kc];
                a[mt][1] = As[(mb + r + 8) * ROWW + kc];
                a[mt][2] = As[(mb + r) * ROWW + kc + 4];
                a[mt][3] = As[(mb + r + 8) * ROWW + kc + 4];
            }
#pragma unroll
            for (int nt = 0; nt < 4; nt++) {
                int nb = warp_n * 32 + nt * 8 + r;
                b[nt][0] = Bs[nb * ROWW + kc];
                b[nt][1] = Bs[nb * ROWW + kc + 4];
            }
#pragma unroll
            for (int mt = 0; mt < 4; mt++)
#pragma unroll
                for (int nt = 0; nt < 4; nt++)
                    mma_tf32(acc[mt][nt], a[mt], b[nt]);
        }
        __syncthreads();
    }

    // Epilogue: add bias, store fp32.
#pragma unroll
    for (int mt = 0; mt < 4; mt++) {
        int row0 = bm + warp_m * 64 + mt * 16 + r;
#pragma unroll
        for (int nt = 0; nt < 4; nt++) {
            int col = bn + warp_n * 32 + nt * 8 + 2 * cq;
            float b0 = __ldg(bias + col), b1 = __ldg(bias + col + 1);
            float2 v0 = make_float2(acc[mt][nt][0] + b0, acc[mt][nt][1] + b1);
            float2 v1 = make_float2(acc[mt][nt][2] + b0, acc[mt][nt][3] + b1);
            *(float2*)&C[(size_t)row0 * H2 + col]       = v0;
            *(float2*)&C[(size_t)(row0 + 8) * H2 + col] = v1;
        }
    }
}

// ---------------- scan ----------------
__device__ __forceinline__ void rv_from_gh(float gate, float hid,
                                           float& rr, float& v) {
    float e = __expf(gate);
    rr = __fdividef(1.f, 1.f + e);        // sigmoid(-gate)
    float z = e * rr;                     // sigmoid(gate)
    float g = (hid >= 0.f) ? (hid + 0.5f)
                           : __fdividef(1.f, 1.f + __expf(-hid));
    v = z * g;
}

// Pass 1: per (chain-quad, chunk) local affine composition.
// 65536 threads: hq bits [0,7), chunk [7,13), b [13,16).
__global__ void __launch_bounds__(256) scan_pass1(
    const float* __restrict__ gh, float* __restrict__ Aout,
    float* __restrict__ Bout)
{
    const int idx = blockIdx.x * 256 + threadIdx.x;
    const int h = (idx & 127) * 4;
    const int c = (idx >> 7) & (NC - 1);
    const int b = idx >> 13;

    const float* gb = gh + ((size_t)b * SS + (size_t)c * CT) * H2 + h;
    float A0 = 1.f, A1 = 1.f, A2 = 1.f, A3 = 1.f;
    float B0 = 0.f, B1 = 0.f, B2 = 0.f, B3 = 0.f;
#pragma unroll 2
    for (int t = 0; t < CT; ++t) {
        float4 gate = *(const float4*)(gb + (size_t)t * H2);
        float4 hid  = *(const float4*)(gb + (size_t)t * H2 + HH);
        float r, v;
        rv_from_gh(gate.x, hid.x, r, v); A0 *= r; B0 = fmaf(r, B0, v);
        rv_from_gh(gate.y, hid.y, r, v); A1 *= r; B1 = fmaf(r, B1, v);
        rv_from_gh(gate.z, hid.z, r, v); A2 *= r; B2 = fmaf(r, B2, v);
        rv_from_gh(gate.w, hid.w, r, v); A3 *= r; B3 = fmaf(r, B3, v);
    }
    const int base = c * NCH + b * 512 + h;
    *(float4*)(Aout + base) = make_float4(A0, A1, A2, A3);
    *(float4*)(Bout + base) = make_float4(B0, B1, B2, B3);
}

// Pass 2: sequential prefix over chunk summaries. 4096 threads.
__global__ void __launch_bounds__(256) scan_pass2(
    const float* __restrict__ A, const float* __restrict__ B,
    float* __restrict__ Hinit, float* __restrict__ last)
{
    const int chain = blockIdx.x * 256 + threadIdx.x;
    float h = 0.5f;
#pragma unroll 8
    for (int c = 0; c < NC; ++c) {
        Hinit[c * NCH + chain] = h;
        h = fmaf(A[c * NCH + chain], h, B[c * NCH + chain]);
    }
    last[chain] = h;
}

// Pass 3: replay each chunk from its initial h, write outputs.
// ROUND_TF32: pre-round stored values to tf32 (used for h1 -> layer-2 GEMM A).
template <int ROUND_TF32>
__global__ void __launch_bounds__(256) scan_pass3(
    const float* __restrict__ gh, const float* __restrict__ Hinit,
    float* __restrict__ out)
{
    const int idx = blockIdx.x * 256 + threadIdx.x;
    const int h = (idx & 127) * 4;
    const int c = (idx >> 7) & (NC - 1);
    const int b = idx >> 13;

    const float* gb = gh + ((size_t)b * SS + (size_t)c * CT) * H2 + h;
    float* ob = out + ((size_t)b * SS + (size_t)c * CT) * HH + h;

    float4 hv = *(const float4*)(Hinit + c * NCH + b * 512 + h);
#pragma unroll 2
    for (int t = 0; t < CT; ++t) {
        float4 gate = *(const float4*)(gb + (size_t)t * H2);
        float4 hid  = *(const float4*)(gb + (size_t)t * H2 + HH);
        float r, v;
        rv_from_gh(gate.x, hid.x, r, v); hv.x = fmaf(r, hv.x, v);
        rv_from_gh(gate.y, hid.y, r, v); hv.y = fmaf(r, hv.y, v);
        rv_from_gh(gate.z, hid.z, r, v); hv.z = fmaf(r, hv.z, v);
        rv_from_gh(gate.w, hid.w, r, v); hv.w = fmaf(r, hv.w, v);
        if (ROUND_TF32) {
            uint4 o;
            o.x = f2tf32(hv.x); o.y = f2tf32(hv.y);
            o.z = f2tf32(hv.z); o.w = f2tf32(hv.w);
            *(uint4*)(ob + (size_t)t * HH) = o;
        } else {
            *(float4*)(ob + (size_t)t * HH) = hv;
        }
    }
}

extern "C" void kernel_launch(void* const* d_in, const int* in_sizes, int n_in,
                              void* d_out, int out_size)
{
    const float* x  = (const float*)d_in[0];
    const float* w0 = (const float*)d_in[1];
    const float* b0 = (const float*)d_in[2];
    const float* w1 = (const float*)d_in[3];
    const float* b1 = (const float*)d_in[4];
    float* out = (float*)d_out;

    float *gh, *h1, *Ab, *Bb, *Hi, *w0r, *w1r;
    cudaGetSymbolAddress((void**)&gh, g_gh);
    cudaGetSymbolAddress((void**)&h1, g_h1);
    cudaGetSymbolAddress((void**)&Ab, g_A);
    cudaGetSymbolAddress((void**)&Bb, g_B);
    cudaGetSymbolAddress((void**)&Hi, g_Hi);
    cudaGetSymbolAddress((void**)&w0r, g_w0r);
    cudaGetSymbolAddress((void**)&w1r, g_w1r);

    cudaFuncSetAttribute(gemm_tf32, cudaFuncAttributeMaxDynamicSharedMemorySize,
                         DYN_SMEM);

    dim3 ggrid(H2 / GBN, MM / GBM);          // (8, 128) = 1024 CTAs
    const int sgrid = (NCH / 4) * NC / 256;  // 256 blocks, 65536 threads

    float* last0 = out + (size_t)MM * HH;
    float* last1 = last0 + (size_t)BB * HH;

    // Pre-round weights to tf32 (round-to-nearest instead of HW truncation).
    round_weights<<<(H2 * DD) / 1024, 256>>>(w0, w0r);
    round_weights<<<(H2 * HH) / 1024, 256>>>(w1, w1r);

    // Layer 1: h1 written pre-rounded to tf32 (feeds GEMM 2 A-side).
    gemm_tf32<<<ggrid, NTHR, DYN_SMEM>>>(x, w0r, b0, gh);
    scan_pass1<<<sgrid, 256>>>(gh, Ab, Bb);
    scan_pass2<<<NCH / 256, 256>>>(Ab, Bb, Hi, last0);
    scan_pass3<1><<<sgrid, 256>>>(gh, Hi, h1);

    // Layer 2
    gemm_tf32<<<ggrid, NTHR, DYN_SMEM>>>(h1, w1r, b1, gh);
    scan_pass1<<<sgrid, 256>>>(gh, Ab, Bb);
    scan_pass2<<<NCH / 256, 256>>>(Ab, Bb, Hi, last1);
    scan_pass3<0><<<sgrid, 256>>>(gh, Hi, out);
}

// round 12
// speedup vs baseline: 1.3171x; 1.3171x over previous
#include <cuda_runtime.h>
#include <cuda_fp16.h>
#include <cstdint>

// Problem constants (fixed shapes from reference setup_inputs)
#define BB 8
#define SS 4096
#define DD 512
#define HH 512
#define H2 1024
#define MM (BB * SS)   // 32768
#define NCH 4096       // B*H chains
#define NC 64          // chunks per chain
#define CT 64          // steps per chunk

#define KK 512         // GEMM K in elements (both layers)
#define NKT 16         // K tiles of 32
#define GBM 128        // CTA M tile
#define GBN 256        // CTA N tile
#define ROWH 20        // smem row stride in 4B words (16 data + 4 pad)
#define STW ((GBM + GBN) * ROWH)        // words per stage = 7680
#define NSTG 3
#define DYN_SMEM (NSTG * STW * 4)       // 92160 B

// Scratch
__device__ float  g_gh[(long long)MM * H2];
__device__ __half g_xh[(long long)MM * DD];
__device__ __half g_h1h[(long long)MM * HH];
__device__ __half g_wh0[H2 * DD];
__device__ __half g_wh1[H2 * HH];
__device__ float  g_A[NC * NCH];
__device__ float  g_B[NC * NCH];
__device__ float  g_Hi[NC * NCH];

__device__ __forceinline__ uint32_t smem_u32(const void* p) {
    uint32_t a;
    asm("{ .reg .u64 t; cvta.to.shared.u64 t, %1; cvt.u32.u64 %0, t; }"
        : "=r"(a) : "l"(p));
    return a;
}
#define CP_ASYNC16(dst, src) \
    asm volatile("cp.async.cg.shared.global [%0], [%1], 16;\n" \
                 :: "r"(dst), "l"(src) : "memory")
#define CP_COMMIT() asm volatile("cp.async.commit_group;\n" ::: "memory")
#define CP_WAIT1()  asm volatile("cp.async.wait_group 1;\n" ::: "memory")

__device__ __forceinline__ void mma_f16(float* c, const uint32_t* a, const uint32_t* b) {
    asm volatile(
        "mma.sync.aligned.m16n8k16.row.col.f32.f16.f16.f32 "
        "{%0,%1,%2,%3}, {%4,%5,%6,%7}, {%8,%9}, {%0,%1,%2,%3};"
        : "+f"(c[0]), "+f"(c[1]), "+f"(c[2]), "+f"(c[3])
        : "r"(a[0]), "r"(a[1]), "r"(a[2]), "r"(a[3]),
          "r"(b[0]), "r"(b[1]));
}

// fp32 -> fp16 (rn), 4 elements per thread.
__global__ void __launch_bounds__(256) convert_f2h(
    const float* __restrict__ in, __half* __restrict__ out)
{
    int i = (blockIdx.x * 256 + threadIdx.x) * 4;
    float4 v = *(const float4*)(in + i);
    __half2 lo = __floats2half2_rn(v.x, v.y);
    __half2 hi = __floats2half2_rn(v.z, v.w);
    uint2 o = make_uint2(*(uint32_t*)&lo, *(uint32_t*)&hi);
    *(uint2*)(out + i) = o;
}

// Issue cp.async for one 32-element K stage: A 128 rows, W 256 rows (half).
__device__ __forceinline__ void stage_copy(
    const __half* __restrict__ A, const __half* __restrict__ W,
    uint32_t sA, uint32_t sB, int bm, int bn, int kt, int tid)
{
    const __half* Ab = A + (size_t)bm * KK + kt * 32;
    const __half* Wb = W + (size_t)bn * KK + kt * 32;
#pragma unroll
    for (int i = 0; i < 2; i++) {               // 512 granules of A
        int g = tid + 256 * i;
        int row = g >> 2, q = g & 3;
        CP_ASYNC16(sA + row * (ROWH * 4) + q * 16,
                   Ab + (size_t)row * KK + q * 8);
    }
#pragma unroll
    for (int i = 0; i < 4; i++) {               // 1024 granules of W
        int g = tid + 256 * i;
        int row = g >> 2, q = g & 3;
        CP_ASYNC16(sB + row * (ROWH * 4) + q * 16,
                   Wb + (size_t)row * KK + q * 8);
    }
    CP_COMMIT();
}

// C[M,1024] = A[M,512] * W[1024,512]^T + bias, fp16 mma m16n8k16 (fp32 accum),
// block tile 128x256, 8 warps (2m x 4n), warp tile 64x64, 3-stage cp.async.
__global__ void __launch_bounds__(256, 1) gemm_f16(
    const __half* __restrict__ A, const __half* __restrict__ W,
    const float* __restrict__ bias, float* __restrict__ C)
{
    extern __shared__ uint32_t dyn[];

    const int tid    = threadIdx.x;
    const int wid    = tid >> 5;
    const int lane   = tid & 31;
    const int warp_m = wid >> 2;       // 0..1 -> 64 rows
    const int warp_n = wid & 3;        // 0..3 -> 64 cols
    const int bm     = blockIdx.y * GBM;
    const int bn     = blockIdx.x * GBN;
    const int r      = lane >> 2;      // 0..7
    const int cq     = lane & 3;       // 0..3

    const uint32_t sbase = smem_u32(dyn);

    float acc[4][8][4];
#pragma unroll
    for (int i = 0; i < 4; i++)
#pragma unroll
        for (int j = 0; j < 8; j++)
#pragma unroll
            for (int w = 0; w < 4; w++) acc[i][j][w] = 0.f;

    // Prefetch stages 0 and 1.
    stage_copy(A, W, sbase, sbase + GBM * ROWH * 4, bm, bn, 0, tid);
    stage_copy(A, W, sbase + STW * 4, sbase + (STW + GBM * ROWH) * 4, bm, bn, 1, tid);

    for (int kt = 0; kt < NKT; kt++) {
        const int s = kt % NSTG;
        CP_WAIT1();
        __syncthreads();

        if (kt + 2 < NKT) {
            const int sp = (kt + 2) % NSTG;
            stage_copy(A, W, sbase + sp * STW * 4,
                       sbase + (sp * STW + GBM * ROWH) * 4, bm, bn, kt + 2, tid);
        }

        const uint32_t* As = dyn + s * STW;
        const uint32_t* Bs = As + GBM * ROWH;

        // 2 k-slices of 16 within the 32-element tile.
#pragma unroll
        for (int ks = 0; ks < 2; ks++) {
            const int kc = ks * 8 + cq;
            uint32_t a[4][4], b[8][2];
#pragma unroll
            for (int mt = 0; mt < 4; mt++) {
                int mb = warp_m * 64 + mt * 16;
                a[mt][0] = As[(mb + r) * ROWH + kc];
                a[mt][1] = As[(mb + r + 8) * ROWH + kc];
                a[mt][2] = As[(mb + r) * ROWH + kc + 4];
                a[mt][3] = As[(mb + r + 8) * ROWH + kc + 4];
            }
#pragma unroll
            for (int nt = 0; nt < 8; nt++) {
                int nb = warp_n * 64 + nt * 8 + r;
                b[nt][0] = Bs[nb * ROWH + kc];
                b[nt][1] = Bs[nb * ROWH + kc + 4];
            }
#pragma unroll
            for (int mt = 0; mt < 4; mt++)
#pragma unroll
                for (int nt = 0; nt < 8; nt++)
                    mma_f16(acc[mt][nt], a[mt], b[nt]);
        }
        __syncthreads();
    }

    // Epilogue: add bias, store fp32.
#pragma unroll
    for (int mt = 0; mt < 4; mt++) {
        int row0 = bm + warp_m * 64 + mt * 16 + r;
#pragma unroll
        for (int nt = 0; nt < 8; nt++) {
            int col = bn + warp_n * 64 + nt * 8 + 2 * cq;
            float b0 = __ldg(bias + col), b1 = __ldg(bias + col + 1);
            float2 v0 = make_float2(acc[mt][nt][0] + b0, acc[mt][nt][1] + b1);
            float2 v1 = make_float2(acc[mt][nt][2] + b0, acc[mt][nt][3] + b1);
            *(float2*)&C[(size_t)row0 * H2 + col]       = v0;
            *(float2*)&C[(size_t)(row0 + 8) * H2 + col] = v1;
        }
    }
}

// ---------------- scan ----------------
__device__ __forceinline__ void rv_from_gh(float gate, float hid,
                                           float& rr, float& v) {
    float e = __expf(gate);
    rr = __fdividef(1.f, 1.f + e);        // sigmoid(-gate)
    float z = e * rr;                     // sigmoid(gate)
    float g = (hid >= 0.f) ? (hid + 0.5f)
                           : __fdividef(1.f, 1.f + __expf(-hid));
    v = z * g;
}

// Pass 1: per (chain-quad, chunk) local affine composition. 65536 threads.
__global__ void __launch_bounds__(256) scan_pass1(
    const float* __restrict__ gh, float* __restrict__ Aout,
    float* __restrict__ Bout)
{
    const int idx = blockIdx.x * 256 + threadIdx.x;
    const int h = (idx & 127) * 4;
    const int c = (idx >> 7) & (NC - 1);
    const int b = idx >> 13;

    const float* gb = gh + ((size_t)b * SS + (size_t)c * CT) * H2 + h;
    float A0 = 1.f, A1 = 1.f, A2 = 1.f, A3 = 1.f;
    float B0 = 0.f, B1 = 0.f, B2 = 0.f, B3 = 0.f;
#pragma unroll 2
    for (int t = 0; t < CT; ++t) {
        float4 gate = *(const float4*)(gb + (size_t)t * H2);
        float4 hid  = *(const float4*)(gb + (size_t)t * H2 + HH);
        float r, v;
        rv_from_gh(gate.x, hid.x, r, v); A0 *= r; B0 = fmaf(r, B0, v);
        rv_from_gh(gate.y, hid.y, r, v); A1 *= r; B1 = fmaf(r, B1, v);
        rv_from_gh(gate.z, hid.z, r, v); A2 *= r; B2 = fmaf(r, B2, v);
        rv_from_gh(gate.w, hid.w, r, v); A3 *= r; B3 = fmaf(r, B3, v);
    }
    const int base = c * NCH + b * 512 + h;
    *(float4*)(Aout + base) = make_float4(A0, A1, A2, A3);
    *(float4*)(Bout + base) = make_float4(B0, B1, B2, B3);
}

// Pass 2: sequential prefix over chunk summaries. 4096 threads.
__global__ void __launch_bounds__(256) scan_pass2(
    const float* __restrict__ A, const float* __restrict__ B,
    float* __restrict__ Hinit, float* __restrict__ last)
{
    const int chain = blockIdx.x * 256 + threadIdx.x;
    float h = 0.5f;
#pragma unroll 8
    for (int c = 0; c < NC; ++c) {
        Hinit[c * NCH + chain] = h;
        h = fmaf(A[c * NCH + chain], h, B[c * NCH + chain]);
    }
    last[chain] = h;
}

// Pass 3: replay each chunk from its initial h.
// OUT_HALF=1: write h1 as fp16 (rn) for the layer-2 GEMM A operand.
template <int OUT_HALF>
__global__ void __launch_bounds__(256) scan_pass3(
    const float* __restrict__ gh, const float* __restrict__ Hinit,
    float* __restrict__ outf, __half* __restrict__ outh)
{
    const int idx = blockIdx.x * 256 + threadIdx.x;
    const int h = (idx & 127) * 4;
    const int c = (idx >> 7) & (NC - 1);
    const int b = idx >> 13;

    const float* gb = gh + ((size_t)b * SS + (size_t)c * CT) * H2 + h;
    const size_t obase = ((size_t)b * SS + (size_t)c * CT) * HH + h;

    float4 hv = *(const float4*)(Hinit + c * NCH + b * 512 + h);
#pragma unroll 2
    for (int t = 0; t < CT; ++t) {
        float4 gate = *(const float4*)(gb + (size_t)t * H2);
        float4 hid  = *(const float4*)(gb + (size_t)t * H2 + HH);
        float r, v;
        rv_from_gh(gate.x, hid.x, r, v); hv.x = fmaf(r, hv.x, v);
        rv_from_gh(gate.y, hid.y, r, v); hv.y = fmaf(r, hv.y, v);
        rv_from_gh(gate.z, hid.z, r, v); hv.z = fmaf(r, hv.z, v);
        rv_from_gh(gate.w, hid.w, r, v); hv.w = fmaf(r, hv.w, v);
        if (OUT_HALF) {
            __half2 lo = __floats2half2_rn(hv.x, hv.y);
            __half2 hi = __floats2half2_rn(hv.z, hv.w);
            uint2 o = make_uint2(*(uint32_t*)&lo, *(uint32_t*)&hi);
            *(uint2*)(outh + obase + (size_t)t * HH) = o;
        } else {
            *(float4*)(outf + obase + (size_t)t * HH) = hv;
        }
    }
}

extern "C" void kernel_launch(void* const* d_in, const int* in_sizes, int n_in,
                              void* d_out, int out_size)
{
    const float* x  = (const float*)d_in[0];
    const float* w0 = (const float*)d_in[1];
    const float* b0 = (const float*)d_in[2];
    const float* w1 = (const float*)d_in[3];
    const float* b1 = (const float*)d_in[4];
    float* out = (float*)d_out;

    float *gh, *Ab, *Bb, *Hi;
    __half *xh, *h1h, *wh0, *wh1;
    cudaGetSymbolAddress((void**)&gh,  g_gh);
    cudaGetSymbolAddress((void**)&xh,  g_xh);
    cudaGetSymbolAddress((void**)&h1h, g_h1h);
    cudaGetSymbolAddress((void**)&wh0, g_wh0);
    cudaGetSymbolAddress((void**)&wh1, g_wh1);
    cudaGetSymbolAddress((void**)&Ab,  g_A);
    cudaGetSymbolAddress((void**)&Bb,  g_B);
    cudaGetSymbolAddress((void**)&Hi,  g_Hi);

    cudaFuncSetAttribute(gemm_f16, cudaFuncAttributeMaxDynamicSharedMemorySize,
                         DYN_SMEM);

    dim3 ggrid(H2 / GBN, MM / GBM);          // (4, 256) = 1024 CTAs
    const int sgrid = (NCH / 4) * NC / 256;  // 256 blocks, 65536 threads

    float* last0 = out + (size_t)MM * HH;
    float* last1 = last0 + (size_t)BB * HH;

    // Convert inputs to fp16 (rn).
    convert_f2h<<<(MM * DD) / 1024, 256>>>(x, xh);
    convert_f2h<<<(H2 * DD) / 1024, 256>>>(w0, wh0);
    convert_f2h<<<(H2 * HH) / 1024, 256>>>(w1, wh1);

    // Layer 1: h1 written as fp16 (feeds GEMM 2 A-side).
    gemm_f16<<<ggrid, 256, DYN_SMEM>>>(xh, wh0, b0, gh);
    scan_pass1<<<sgrid, 256>>>(gh, Ab, Bb);
    scan_pass2<<<NCH / 256, 256>>>(Ab, Bb, Hi, last0);
    scan_pass3<1><<<sgrid, 256>>>(gh, Hi, nullptr, h1h);

    // Layer 2
    gemm_f16<<<ggrid, 256, DYN_SMEM>>>(h1h, wh1, b1, gh);
    scan_pass1<<<sgrid, 256>>>(gh, Ab, Bb);
    scan_pass2<<<NCH / 256, 256>>>(Ab, Bb, Hi, last1);
    scan_pass3<0><<<sgrid, 256>>>(gh, Hi, out, nullptr);
}